// round 2
// baseline (speedup 1.0000x reference)
#include <cuda_runtime.h>
#include <math.h>

#define BSZ 2
#define SEQ 2048
#define DIM 4096
#define NH 32
#define NKV 8
#define HD 128
#define NREP 4

// Scratch (static device globals — allocation-free)
__device__ float g_q[(size_t)BSZ * SEQ * NH * HD];   // 64 MB
__device__ float g_k[(size_t)BSZ * SEQ * NKV * HD];  // 16 MB
__device__ float g_v[(size_t)BSZ * SEQ * NKV * HD];  // 16 MB
__device__ float g_o[(size_t)BSZ * SEQ * NH * HD];   // 64 MB

// ---------------------------------------------------------------------------
// SGEMM: C[M,N] = A[M,K] @ B[K,N], all row-major, fp32.
// 128x128 tile, BK=16, 256 threads, 8x8 register blocking.
// Requires M%128==0, N%128==0, K%16==0 (true for all our shapes).
// ---------------------------------------------------------------------------
__global__ void __launch_bounds__(256) sgemm128(const float* __restrict__ A,
                                                const float* __restrict__ B,
                                                float* __restrict__ C,
                                                int M, int N, int K) {
    __shared__ float As[16][132];  // padded, stored transposed: As[k][m]
    __shared__ float Bs[16][128];

    const int tid = threadIdx.x;
    const int tx = tid & 15;
    const int ty = tid >> 4;
    const int bx = blockIdx.x;  // N direction
    const int by = blockIdx.y;  // M direction

    const int ar = tid >> 2;         // 0..63 (A tile row, +64 on 2nd iter)
    const int ac = (tid & 3) * 4;    // 0,4,8,12
    const int br = tid >> 5;         // 0..7 (+8 on 2nd iter)
    const int bc = (tid & 31) * 4;   // 0..124

    const float* Ab = A + (size_t)(by * 128) * K;
    const float* Bb = B + bx * 128;

    float acc[8][8];
#pragma unroll
    for (int i = 0; i < 8; i++)
#pragma unroll
        for (int j = 0; j < 8; j++) acc[i][j] = 0.0f;

    for (int k0 = 0; k0 < K; k0 += 16) {
#pragma unroll
        for (int i = 0; i < 2; i++) {
            float4 v = *(const float4*)&Ab[(size_t)(ar + i * 64) * K + k0 + ac];
            As[ac + 0][ar + i * 64] = v.x;
            As[ac + 1][ar + i * 64] = v.y;
            As[ac + 2][ar + i * 64] = v.z;
            As[ac + 3][ar + i * 64] = v.w;
        }
#pragma unroll
        for (int i = 0; i < 2; i++) {
            float4 v = *(const float4*)&Bb[(size_t)(k0 + br + i * 8) * N + bc];
            *(float4*)&Bs[br + i * 8][bc] = v;
        }
        __syncthreads();

#pragma unroll
        for (int kk = 0; kk < 16; kk++) {
            float a[8], b[8];
#pragma unroll
            for (int i = 0; i < 8; i++) a[i] = As[kk][ty * 8 + i];
#pragma unroll
            for (int j = 0; j < 8; j++) b[j] = Bs[kk][tx * 8 + j];
#pragma unroll
            for (int i = 0; i < 8; i++)
#pragma unroll
                for (int j = 0; j < 8; j++) acc[i][j] = fmaf(a[i], b[j], acc[i][j]);
        }
        __syncthreads();
    }

#pragma unroll
    for (int i = 0; i < 8; i++) {
        size_t row = (size_t)(by * 128 + ty * 8 + i) * N + bx * 128 + tx * 8;
        float4 v0 = make_float4(acc[i][0], acc[i][1], acc[i][2], acc[i][3]);
        float4 v1 = make_float4(acc[i][4], acc[i][5], acc[i][6], acc[i][7]);
        *(float4*)&C[row + 0] = v0;
        *(float4*)&C[row + 4] = v1;
    }
}

// ---------------------------------------------------------------------------
// RoPE, interleaved pairs: (d0,d1) per pair i, cos/sin indexed [s, i].
// ---------------------------------------------------------------------------
__global__ void rope_kernel(float* __restrict__ t, const float* __restrict__ cosT,
                            const float* __restrict__ sinT, int nh, int total) {
    int i = blockIdx.x * blockDim.x + threadIdx.x;
    if (i >= total) return;
    int pair = i & 63;
    int h = (i >> 6) % nh;
    int bs = i / (64 * nh);        // b*SEQ + s
    int s = bs & (SEQ - 1);
    size_t base = ((size_t)bs * nh + h) * HD + 2 * pair;
    float a = t[base];
    float b = t[base + 1];
    float c = cosT[s * 64 + pair];
    float sn = sinT[s * 64 + pair];
    t[base] = a * c - b * sn;
    t[base + 1] = a * sn + b * c;
}

// ---------------------------------------------------------------------------
// Flash attention, fp32, causal, GQA.
// Block: 256 threads handles one (b, h, q-tile of 64). Iterates k-tiles of 64.
// Online softmax with per-row running max/sum in smem.
// ---------------------------------------------------------------------------
#define AQ 64
#define AKT 64
#define RS 133   // row stride (pad) for Q/K/V tiles
#define SSS 65   // row stride for score tile

__global__ void __launch_bounds__(256) attn_kernel() {
    extern __shared__ float sm[];
    float* Qs = sm;                       // AQ * RS
    float* KVs = Qs + AQ * RS;            // AKT * RS
    float* Ss = KVs + AKT * RS;           // AQ * SSS
    float* mRow = Ss + AQ * SSS;          // AQ
    float* lRow = mRow + AQ;              // AQ
    float* fRow = lRow + AQ;              // AQ

    const int tid = threadIdx.x;
    const int tx = tid & 15;
    const int ty = tid >> 4;
    const int bh = blockIdx.x;            // 0..BSZ*NH-1
    const int b = bh / NH;
    const int h = bh % NH;
    const int kvh = h / NREP;
    const int qt = gridDim.y - 1 - blockIdx.y;  // big tiles launch first
    const int q0 = qt * AQ;

    const float scale = 0.08838834764831845f;  // 1/sqrt(128)

    // Load Q tile (scaled)
#pragma unroll
    for (int it = 0; it < 8; it++) {
        int idx = tid + it * 256;
        int r = idx >> 5;
        int c = (idx & 31) * 4;
        const float* src = g_q + ((size_t)(b * SEQ + q0 + r) * NH + h) * HD + c;
        float4 v = *(const float4*)src;
        Qs[r * RS + c + 0] = v.x * scale;
        Qs[r * RS + c + 1] = v.y * scale;
        Qs[r * RS + c + 2] = v.z * scale;
        Qs[r * RS + c + 3] = v.w * scale;
    }
    if (tid < AQ) {
        mRow[tid] = -1e30f;
        lRow[tid] = 0.0f;
    }

    float o[4][8];
#pragma unroll
    for (int i = 0; i < 4; i++)
#pragma unroll
        for (int j = 0; j < 8; j++) o[i][j] = 0.0f;

    for (int kt = 0; kt <= qt; kt++) {
        const int k0 = kt * AKT;
        // Load K tile
#pragma unroll
        for (int it = 0; it < 8; it++) {
            int idx = tid + it * 256;
            int r = idx >> 5;
            int c = (idx & 31) * 4;
            const float* src = g_k + ((size_t)(b * SEQ + k0 + r) * NKV + kvh) * HD + c;
            float4 v = *(const float4*)src;
            KVs[r * RS + c + 0] = v.x;
            KVs[r * RS + c + 1] = v.y;
            KVs[r * RS + c + 2] = v.z;
            KVs[r * RS + c + 3] = v.w;
        }
        __syncthreads();

        // S = Q @ K^T (each thread 4x4)
        float s4[4][4];
#pragma unroll
        for (int i = 0; i < 4; i++)
#pragma unroll
            for (int j = 0; j < 4; j++) s4[i][j] = 0.0f;

        for (int d = 0; d < HD; d++) {
            float a[4], bb[4];
#pragma unroll
            for (int i = 0; i < 4; i++) a[i] = Qs[(ty * 4 + i) * RS + d];
#pragma unroll
            for (int j = 0; j < 4; j++) bb[j] = KVs[(tx * 4 + j) * RS + d];
#pragma unroll
            for (int i = 0; i < 4; i++)
#pragma unroll
                for (int j = 0; j < 4; j++) s4[i][j] = fmaf(a[i], bb[j], s4[i][j]);
        }

        const bool diag = (kt == qt);
#pragma unroll
        for (int i = 0; i < 4; i++)
#pragma unroll
            for (int j = 0; j < 4; j++) {
                float v = s4[i][j];
                if (diag && (k0 + tx * 4 + j) > (q0 + ty * 4 + i)) v = -1e30f;
                Ss[(ty * 4 + i) * SSS + tx * 4 + j] = v;
            }
        __syncthreads();

        // Load V tile into KVs (K no longer needed); softmax on rows (tid<64)
#pragma unroll
        for (int it = 0; it < 8; it++) {
            int idx = tid + it * 256;
            int r = idx >> 5;
            int c = (idx & 31) * 4;
            const float* src = g_v + ((size_t)(b * SEQ + k0 + r) * NKV + kvh) * HD + c;
            float4 v = *(const float4*)src;
            KVs[r * RS + c + 0] = v.x;
            KVs[r * RS + c + 1] = v.y;
            KVs[r * RS + c + 2] = v.z;
            KVs[r * RS + c + 3] = v.w;
        }
        if (tid < AQ) {
            const int r = tid;
            float m_old = mRow[r];
            float mx = m_old;
#pragma unroll 8
            for (int j = 0; j < AKT; j++) mx = fmaxf(mx, Ss[r * SSS + j]);
            float f = __expf(m_old - mx);
            float sum = 0.0f;
#pragma unroll 8
            for (int j = 0; j < AKT; j++) {
                float e = __expf(Ss[r * SSS + j] - mx);
                Ss[r * SSS + j] = e;
                sum += e;
            }
            mRow[r] = mx;
            lRow[r] = lRow[r] * f + sum;
            fRow[r] = f;
        }
        __syncthreads();

        // Rescale accumulators + O += P @ V
        float f4[4];
#pragma unroll
        for (int i = 0; i < 4; i++) f4[i] = fRow[ty * 4 + i];
#pragma unroll
        for (int i = 0; i < 4; i++)
#pragma unroll
            for (int j = 0; j < 8; j++) o[i][j] *= f4[i];

        for (int k = 0; k < AKT; k++) {
            float p[4], vv[8];
#pragma unroll
            for (int i = 0; i < 4; i++) p[i] = Ss[(ty * 4 + i) * SSS + k];
#pragma unroll
            for (int j = 0; j < 8; j++) vv[j] = KVs[k * RS + tx * 8 + j];
#pragma unroll
            for (int i = 0; i < 4; i++)
#pragma unroll
                for (int j = 0; j < 8; j++) o[i][j] = fmaf(p[i], vv[j], o[i][j]);
        }
        __syncthreads();
    }

    // Epilogue: divide by l, store to g_o (b, q, h, d)
    float inv4[4];
#pragma unroll
    for (int i = 0; i < 4; i++) inv4[i] = 1.0f / lRow[ty * 4 + i];
#pragma unroll
    for (int i = 0; i < 4; i++) {
        float* dst = g_o + ((size_t)(b * SEQ + q0 + ty * 4 + i) * NH + h) * HD + tx * 8;
#pragma unroll
        for (int j = 0; j < 8; j++) dst[j] = o[i][j] * inv4[i];
    }
}

// ---------------------------------------------------------------------------
extern "C" void kernel_launch(void* const* d_in, const int* in_sizes, int n_in,
                              void* d_out, int out_size) {
    const float* x = (const float*)d_in[0];
    const float* wq = (const float*)d_in[1];
    const float* wk = (const float*)d_in[2];
    const float* wv = (const float*)d_in[3];
    const float* wo = (const float*)d_in[4];
    const float* fcos = (const float*)d_in[7];
    const float* fsin = (const float*)d_in[8];
    float* out = (float*)d_out;

    float *q, *k, *v, *o;
    cudaGetSymbolAddress((void**)&q, g_q);
    cudaGetSymbolAddress((void**)&k, g_k);
    cudaGetSymbolAddress((void**)&v, g_v);
    cudaGetSymbolAddress((void**)&o, g_o);

    const int M = BSZ * SEQ;  // 4096

    // QKV projections
    sgemm128<<<dim3(DIM / 128, M / 128), 256>>>(x, wq, q, M, NH * HD, DIM);
    sgemm128<<<dim3((NKV * HD) / 128, M / 128), 256>>>(x, wk, k, M, NKV * HD, DIM);
    sgemm128<<<dim3((NKV * HD) / 128, M / 128), 256>>>(x, wv, v, M, NKV * HD, DIM);

    // RoPE on Q and K
    {
        int totq = BSZ * SEQ * NH * 64;
        rope_kernel<<<(totq + 255) / 256, 256>>>(q, fcos, fsin, NH, totq);
        int totk = BSZ * SEQ * NKV * 64;
        rope_kernel<<<(totk + 255) / 256, 256>>>(k, fcos, fsin, NKV, totk);
    }

    // Flash attention
    {
        const int smem = (AQ * RS + AKT * RS + AQ * SSS + 3 * AQ) * sizeof(float);
        cudaFuncSetAttribute(attn_kernel, cudaFuncAttributeMaxDynamicSharedMemorySize, smem);
        attn_kernel<<<dim3(BSZ * NH, SEQ / AQ), 256, smem>>>();
    }

    // Output projection
    sgemm128<<<dim3(DIM / 128, M / 128), 256>>>(o, wo, out, M, DIM, DIM);
}

// round 4
// speedup vs baseline: 3.0532x; 3.0532x over previous
#include <cuda_runtime.h>
#include <cuda_bf16.h>
#include <stdint.h>
#include <math.h>

#define BSZ 2
#define SEQ 2048
#define DIM 4096
#define NH 32
#define NKV 8
#define HD 128
#define NREP 4
#define MTOK 4096  // BSZ*SEQ

// ---------------- device scratch (allocation-free) ----------------
__device__ float g_q[(size_t)MTOK * NH * HD];
__device__ float g_k[(size_t)MTOK * NKV * HD];
__device__ float g_v[(size_t)MTOK * NKV * HD];
__device__ float g_o[(size_t)MTOK * NH * HD];

__device__ uint16_t g_xh[(size_t)MTOK * DIM], g_xl[(size_t)MTOK * DIM];
__device__ uint16_t g_wqh[(size_t)DIM * DIM], g_wql[(size_t)DIM * DIM];              // [N][K]
__device__ uint16_t g_wkh[(size_t)DIM * NKV * HD], g_wkl[(size_t)DIM * NKV * HD];    // [N][K]
__device__ uint16_t g_wvh[(size_t)DIM * NKV * HD], g_wvl[(size_t)DIM * NKV * HD];    // [N][K]
__device__ uint16_t g_woh[(size_t)DIM * DIM], g_wol[(size_t)DIM * DIM];              // [N][K]
__device__ uint16_t g_ooh[(size_t)MTOK * DIM], g_ool[(size_t)MTOK * DIM];

// ---------------- helpers ----------------
__device__ __forceinline__ void fsplit(float v, uint16_t& hb, uint16_t& lb) {
    __nv_bfloat16 h = __float2bfloat16(v);
    float r = v - __bfloat162float(h);
    hb = __bfloat16_as_ushort(h);
    lb = __bfloat16_as_ushort(__float2bfloat16(r));
}

__device__ __forceinline__ void cpasync16(void* dst, const void* src) {
    uint32_t d = (uint32_t)__cvta_generic_to_shared(dst);
    asm volatile("cp.async.cg.shared.global [%0], [%1], 16;\n" ::"r"(d), "l"(src));
}
#define CPCOMMIT asm volatile("cp.async.commit_group;\n" ::)
#define CPWAIT0 asm volatile("cp.async.wait_group 0;\n" ::)

__device__ __forceinline__ void ldsm4(uint32_t* d, uint32_t addr) {
    asm volatile("ldmatrix.sync.aligned.m8n8.x4.shared.b16 {%0,%1,%2,%3}, [%4];"
                 : "=r"(d[0]), "=r"(d[1]), "=r"(d[2]), "=r"(d[3])
                 : "r"(addr));
}

__device__ __forceinline__ void mma_bs(float* c, const uint32_t* a, uint32_t b0, uint32_t b1) {
    asm volatile(
        "mma.sync.aligned.m16n8k16.row.col.f32.bf16.bf16.f32 "
        "{%0,%1,%2,%3}, {%4,%5,%6,%7}, {%8,%9}, {%0,%1,%2,%3};"
        : "+f"(c[0]), "+f"(c[1]), "+f"(c[2]), "+f"(c[3])
        : "r"(a[0]), "r"(a[1]), "r"(a[2]), "r"(a[3]), "r"(b0), "r"(b1));
}

// ---------------- prep kernels ----------------
__global__ void split_f32(const float* __restrict__ src, uint16_t* __restrict__ h,
                          uint16_t* __restrict__ l, size_t n4) {
    size_t i = (size_t)(blockIdx.x * blockDim.x + threadIdx.x);
    if (i >= n4) return;
    float4 v = *(const float4*)(src + i * 4);
    ushort4 hh, ll;
    fsplit(v.x, hh.x, ll.x);
    fsplit(v.y, hh.y, ll.y);
    fsplit(v.z, hh.z, ll.z);
    fsplit(v.w, hh.w, ll.w);
    *(ushort4*)(h + i * 4) = hh;
    *(ushort4*)(l + i * 4) = ll;
}

// wh[n][k] = split(w[k][n]);  w is [K][N]
__global__ void tsplit_w(const float* __restrict__ w, uint16_t* __restrict__ wh,
                         uint16_t* __restrict__ wl, int K, int N) {
    __shared__ float t[32][33];
    int n0 = blockIdx.x * 32, k0 = blockIdx.y * 32;
    int tx = threadIdx.x, ty = threadIdx.y;
#pragma unroll
    for (int i = 0; i < 32; i += 8)
        t[ty + i][tx] = w[(size_t)(k0 + ty + i) * N + n0 + tx];
    __syncthreads();
#pragma unroll
    for (int i = 0; i < 32; i += 8) {
        int nn = ty + i, kk = tx;
        uint16_t hb, lb;
        fsplit(t[kk][nn], hb, lb);
        wh[(size_t)(n0 + nn) * K + k0 + kk] = hb;
        wl[(size_t)(n0 + nn) * K + k0 + kk] = lb;
    }
}

// ---------------------------------------------------------------------------
// hi/lo-split bf16 tensor-core GEMM: C[M,N] = A[M,K] @ B[N,K]^T
// A row-major [M][K] (hi/lo planes), B row-major [N][K] (hi/lo planes), C fp32.
// 128x128 CTA tile, BK=32, 8 warps (4M x 2N), cp.async double buffer.
// ---------------------------------------------------------------------------
__global__ void __launch_bounds__(256) hgemm(
    const uint16_t* __restrict__ Ah, const uint16_t* __restrict__ Al,
    const uint16_t* __restrict__ Bh, const uint16_t* __restrict__ Bl,
    float* __restrict__ C, int M, int N, int K) {
    extern __shared__ uint16_t smem[];  // 2 stages * 16384 u16
    const int tid = threadIdx.x, lane = tid & 31, warp = tid >> 5;
    const int wm = warp >> 1, wn = warp & 1;
    const size_t Arow0 = (size_t)blockIdx.y * 128;
    const size_t Brow0 = (size_t)blockIdx.x * 128;

    float acc[2][8][4];
#pragma unroll
    for (int mt = 0; mt < 2; mt++)
#pragma unroll
        for (int nt = 0; nt < 8; nt++)
#pragma unroll
            for (int i = 0; i < 4; i++) acc[mt][nt][i] = 0.0f;

    auto load_stage = [&](int st, int k0) {
        uint16_t* s = smem + st * 16384;
#pragma unroll
        for (int i = 0; i < 2; i++) {
            int idx = tid + i * 256;
            int r = idx >> 2, c = idx & 3;
            int sc = c ^ ((r >> 1) & 3);
            cpasync16(s + r * 32 + sc * 8, Ah + (Arow0 + r) * K + k0 + c * 8);
            cpasync16(s + 4096 + r * 32 + sc * 8, Al + (Arow0 + r) * K + k0 + c * 8);
            cpasync16(s + 8192 + r * 32 + sc * 8, Bh + (Brow0 + r) * K + k0 + c * 8);
            cpasync16(s + 12288 + r * 32 + sc * 8, Bl + (Brow0 + r) * K + k0 + c * 8);
        }
    };

    auto compute_stage = [&](int st) {
        uint16_t* s = smem + st * 16384;
#pragma unroll
        for (int ks = 0; ks < 2; ks++) {
            uint32_t af[2][2][4];  // [plane][mt]
#pragma unroll
            for (int mt = 0; mt < 2; mt++) {
                int r = wm * 32 + mt * 16 + (lane & 15);
                int c = ks * 2 + (lane >> 4);
                int sc = c ^ ((r >> 1) & 3);
                uint32_t a0 = (uint32_t)__cvta_generic_to_shared(s + r * 32 + sc * 8);
                ldsm4(af[0][mt], a0);
                ldsm4(af[1][mt], a0 + 4096 * 2);
            }
            uint32_t bf[2][4][4];  // [plane][pair] -> pair covers n-tiles 2p,2p+1
#pragma unroll
            for (int np = 0; np < 4; np++) {
                int r = wn * 64 + np * 16 + ((lane >> 4) & 1) * 8 + (lane & 7);
                int c = ks * 2 + ((lane >> 3) & 1);
                int sc = c ^ ((r >> 1) & 3);
                uint32_t a0 = (uint32_t)__cvta_generic_to_shared(s + 8192 + r * 32 + sc * 8);
                ldsm4(bf[0][np], a0);
                ldsm4(bf[1][np], a0 + 4096 * 2);
            }
#pragma unroll
            for (int mt = 0; mt < 2; mt++)
#pragma unroll
                for (int nt = 0; nt < 8; nt++) {
                    uint32_t b0h = bf[0][nt >> 1][(nt & 1) * 2];
                    uint32_t b1h = bf[0][nt >> 1][(nt & 1) * 2 + 1];
                    uint32_t b0l = bf[1][nt >> 1][(nt & 1) * 2];
                    uint32_t b1l = bf[1][nt >> 1][(nt & 1) * 2 + 1];
                    mma_bs(acc[mt][nt], af[0][mt], b0h, b1h);  // Ah*Bh
                    mma_bs(acc[mt][nt], af[1][mt], b0h, b1h);  // Al*Bh
                    mma_bs(acc[mt][nt], af[0][mt], b0l, b1l);  // Ah*Bl
                }
        }
    };

    load_stage(0, 0);
    CPCOMMIT;
    const int NKI = K >> 5;
    for (int kt = 0; kt < NKI; kt++) {
        CPWAIT0;
        __syncthreads();
        if (kt + 1 < NKI) {
            load_stage((kt + 1) & 1, (kt + 1) * 32);
            CPCOMMIT;
        }
        compute_stage(kt & 1);
        __syncthreads();
    }

#pragma unroll
    for (int mt = 0; mt < 2; mt++)
#pragma unroll
        for (int nt = 0; nt < 8; nt++) {
            size_t row = Arow0 + wm * 32 + mt * 16 + (lane >> 2);
            size_t col = Brow0 + wn * 64 + nt * 8 + (lane & 3) * 2;
            *(float2*)&C[row * N + col] = make_float2(acc[mt][nt][0], acc[mt][nt][1]);
            *(float2*)&C[(row + 8) * N + col] = make_float2(acc[mt][nt][2], acc[mt][nt][3]);
        }
}

// ---------------------------------------------------------------------------
// RoPE (unchanged, fp32)
// ---------------------------------------------------------------------------
__global__ void rope_kernel(float* __restrict__ t, const float* __restrict__ cosT,
                            const float* __restrict__ sinT, int nh, int total) {
    int i = blockIdx.x * blockDim.x + threadIdx.x;
    if (i >= total) return;
    int pair = i & 63;
    int h = (i >> 6) % nh;
    int bs = i / (64 * nh);
    int s = bs & (SEQ - 1);
    size_t base = ((size_t)bs * nh + h) * HD + 2 * pair;
    float a = t[base];
    float b = t[base + 1];
    float c = cosT[s * 64 + pair];
    float sn = sinT[s * 64 + pair];
    t[base] = a * c - b * sn;
    t[base + 1] = a * sn + b * c;
}

// ---------------------------------------------------------------------------
// Flash attention, fp32, causal, GQA (unchanged from passing baseline)
// ---------------------------------------------------------------------------
#define AQ 64
#define AKT 64
#define RS 133
#define SSS 65

__global__ void __launch_bounds__(256) attn_kernel() {
    extern __shared__ float sm[];
    float* Qs = sm;
    float* KVs = Qs + AQ * RS;
    float* Ss = KVs + AKT * RS;
    float* mRow = Ss + AQ * SSS;
    float* lRow = mRow + AQ;
    float* fRow = lRow + AQ;

    const int tid = threadIdx.x;
    const int tx = tid & 15;
    const int ty = tid >> 4;
    const int bh = blockIdx.x;
    const int b = bh / NH;
    const int h = bh % NH;
    const int kvh = h / NREP;
    const int qt = gridDim.y - 1 - blockIdx.y;
    const int q0 = qt * AQ;

    const float scale = 0.08838834764831845f;

#pragma unroll
    for (int it = 0; it < 8; it++) {
        int idx = tid + it * 256;
        int r = idx >> 5;
        int c = (idx & 31) * 4;
        const float* src = g_q + ((size_t)(b * SEQ + q0 + r) * NH + h) * HD + c;
        float4 v = *(const float4*)src;
        Qs[r * RS + c + 0] = v.x * scale;
        Qs[r * RS + c + 1] = v.y * scale;
        Qs[r * RS + c + 2] = v.z * scale;
        Qs[r * RS + c + 3] = v.w * scale;
    }
    if (tid < AQ) {
        mRow[tid] = -1e30f;
        lRow[tid] = 0.0f;
    }

    float o[4][8];
#pragma unroll
    for (int i = 0; i < 4; i++)
#pragma unroll
        for (int j = 0; j < 8; j++) o[i][j] = 0.0f;

    for (int kt = 0; kt <= qt; kt++) {
        const int k0 = kt * AKT;
#pragma unroll
        for (int it = 0; it < 8; it++) {
            int idx = tid + it * 256;
            int r = idx >> 5;
            int c = (idx & 31) * 4;
            const float* src = g_k + ((size_t)(b * SEQ + k0 + r) * NKV + kvh) * HD + c;
            float4 v = *(const float4*)src;
            KVs[r * RS + c + 0] = v.x;
            KVs[r * RS + c + 1] = v.y;
            KVs[r * RS + c + 2] = v.z;
            KVs[r * RS + c + 3] = v.w;
        }
        __syncthreads();

        float s4[4][4];
#pragma unroll
        for (int i = 0; i < 4; i++)
#pragma unroll
            for (int j = 0; j < 4; j++) s4[i][j] = 0.0f;

        for (int d = 0; d < HD; d++) {
            float a[4], bb[4];
#pragma unroll
            for (int i = 0; i < 4; i++) a[i] = Qs[(ty * 4 + i) * RS + d];
#pragma unroll
            for (int j = 0; j < 4; j++) bb[j] = KVs[(tx * 4 + j) * RS + d];
#pragma unroll
            for (int i = 0; i < 4; i++)
#pragma unroll
                for (int j = 0; j < 4; j++) s4[i][j] = fmaf(a[i], bb[j], s4[i][j]);
        }

        const bool diag = (kt == qt);
#pragma unroll
        for (int i = 0; i < 4; i++)
#pragma unroll
            for (int j = 0; j < 4; j++) {
                float v = s4[i][j];
                if (diag && (k0 + tx * 4 + j) > (q0 + ty * 4 + i)) v = -1e30f;
                Ss[(ty * 4 + i) * SSS + tx * 4 + j] = v;
            }
        __syncthreads();

#pragma unroll
        for (int it = 0; it < 8; it++) {
            int idx = tid + it * 256;
            int r = idx >> 5;
            int c = (idx & 31) * 4;
            const float* src = g_v + ((size_t)(b * SEQ + k0 + r) * NKV + kvh) * HD + c;
            float4 v = *(const float4*)src;
            KVs[r * RS + c + 0] = v.x;
            KVs[r * RS + c + 1] = v.y;
            KVs[r * RS + c + 2] = v.z;
            KVs[r * RS + c + 3] = v.w;
        }
        if (tid < AQ) {
            const int r = tid;
            float m_old = mRow[r];
            float mx = m_old;
#pragma unroll 8
            for (int j = 0; j < AKT; j++) mx = fmaxf(mx, Ss[r * SSS + j]);
            float f = __expf(m_old - mx);
            float sum = 0.0f;
#pragma unroll 8
            for (int j = 0; j < AKT; j++) {
                float e = __expf(Ss[r * SSS + j] - mx);
                Ss[r * SSS + j] = e;
                sum += e;
            }
            mRow[r] = mx;
            lRow[r] = lRow[r] * f + sum;
            fRow[r] = f;
        }
        __syncthreads();

        float f4[4];
#pragma unroll
        for (int i = 0; i < 4; i++) f4[i] = fRow[ty * 4 + i];
#pragma unroll
        for (int i = 0; i < 4; i++)
#pragma unroll
            for (int j = 0; j < 8; j++) o[i][j] *= f4[i];

        for (int k = 0; k < AKT; k++) {
            float p[4], vv[8];
#pragma unroll
            for (int i = 0; i < 4; i++) p[i] = Ss[(ty * 4 + i) * SSS + k];
#pragma unroll
            for (int j = 0; j < 8; j++) vv[j] = KVs[k * RS + tx * 8 + j];
#pragma unroll
            for (int i = 0; i < 4; i++)
#pragma unroll
                for (int j = 0; j < 8; j++) o[i][j] = fmaf(p[i], vv[j], o[i][j]);
        }
        __syncthreads();
    }

    float inv4[4];
#pragma unroll
    for (int i = 0; i < 4; i++) inv4[i] = 1.0f / lRow[ty * 4 + i];
#pragma unroll
    for (int i = 0; i < 4; i++) {
        float* dst = g_o + ((size_t)(b * SEQ + q0 + ty * 4 + i) * NH + h) * HD + tx * 8;
#pragma unroll
        for (int j = 0; j < 8; j++) dst[j] = o[i][j] * inv4[i];
    }
}

// ---------------------------------------------------------------------------
extern "C" void kernel_launch(void* const* d_in, const int* in_sizes, int n_in,
                              void* d_out, int out_size) {
    const float* x = (const float*)d_in[0];
    const float* wq = (const float*)d_in[1];
    const float* wk = (const float*)d_in[2];
    const float* wv = (const float*)d_in[3];
    const float* wo = (const float*)d_in[4];
    const float* fcos = (const float*)d_in[7];
    const float* fsin = (const float*)d_in[8];
    float* out = (float*)d_out;

    float *q, *k, *v, *o;
    cudaGetSymbolAddress((void**)&q, g_q);
    cudaGetSymbolAddress((void**)&k, g_k);
    cudaGetSymbolAddress((void**)&v, g_v);
    cudaGetSymbolAddress((void**)&o, g_o);
    uint16_t *xh, *xl, *wqh, *wql, *wkh, *wkl, *wvh, *wvl, *woh, *wol, *ooh, *ool;
    cudaGetSymbolAddress((void**)&xh, g_xh);
    cudaGetSymbolAddress((void**)&xl, g_xl);
    cudaGetSymbolAddress((void**)&wqh, g_wqh);
    cudaGetSymbolAddress((void**)&wql, g_wql);
    cudaGetSymbolAddress((void**)&wkh, g_wkh);
    cudaGetSymbolAddress((void**)&wkl, g_wkl);
    cudaGetSymbolAddress((void**)&wvh, g_wvh);
    cudaGetSymbolAddress((void**)&wvl, g_wvl);
    cudaGetSymbolAddress((void**)&woh, g_woh);
    cudaGetSymbolAddress((void**)&wol, g_wol);
    cudaGetSymbolAddress((void**)&ooh, g_ooh);
    cudaGetSymbolAddress((void**)&ool, g_ool);

    const int M = MTOK;  // 4096
    static bool attr_set = false;
    if (!attr_set) {
        cudaFuncSetAttribute(hgemm, cudaFuncAttributeMaxDynamicSharedMemorySize, 65536);
        const int asmem = (AQ * RS + AKT * RS + AQ * SSS + 3 * AQ) * sizeof(float);
        cudaFuncSetAttribute(attn_kernel, cudaFuncAttributeMaxDynamicSharedMemorySize, asmem);
        attr_set = true;
    }

    // Split inputs + transpose/split weights
    split_f32<<<(M * DIM / 4 + 255) / 256, 256>>>(x, xh, xl, (size_t)M * DIM / 4);
    tsplit_w<<<dim3(DIM / 32, DIM / 32), dim3(32, 8)>>>(wq, wqh, wql, DIM, DIM);
    tsplit_w<<<dim3(NKV * HD / 32, DIM / 32), dim3(32, 8)>>>(wk, wkh, wkl, DIM, NKV * HD);
    tsplit_w<<<dim3(NKV * HD / 32, DIM / 32), dim3(32, 8)>>>(wv, wvh, wvl, DIM, NKV * HD);
    tsplit_w<<<dim3(DIM / 32, DIM / 32), dim3(32, 8)>>>(wo, woh, wol, DIM, DIM);

    // QKV projections (tensor cores)
    hgemm<<<dim3(DIM / 128, M / 128), 256, 65536>>>(xh, xl, wqh, wql, q, M, DIM, DIM);
    hgemm<<<dim3(NKV * HD / 128, M / 128), 256, 65536>>>(xh, xl, wkh, wkl, k, M, NKV * HD, DIM);
    hgemm<<<dim3(NKV * HD / 128, M / 128), 256, 65536>>>(xh, xl, wvh, wvl, v, M, NKV * HD, DIM);

    // RoPE
    {
        int totq = MTOK * NH * 64;
        rope_kernel<<<(totq + 255) / 256, 256>>>(q, fcos, fsin, NH, totq);
        int totk = MTOK * NKV * 64;
        rope_kernel<<<(totk + 255) / 256, 256>>>(k, fcos, fsin, NKV, totk);
    }

    // Flash attention (fp32)
    {
        const int smem = (AQ * RS + AKT * RS + AQ * SSS + 3 * AQ) * sizeof(float);
        attn_kernel<<<dim3(BSZ * NH, SEQ / AQ), 256, smem>>>();
    }

    // Split attention output, then O projection (tensor cores)
    split_f32<<<(M * DIM / 4 + 255) / 256, 256>>>(o, ooh, ool, (size_t)M * DIM / 4);
    hgemm<<<dim3(DIM / 128, M / 128), 256, 65536>>>(ooh, ool, woh, wol, out, M, DIM, DIM);
}

// round 7
// speedup vs baseline: 4.1579x; 1.3618x over previous
#include <cuda_runtime.h>
#include <cuda_bf16.h>
#include <stdint.h>
#include <math.h>

#define BSZ 2
#define SEQ 2048
#define DIM 4096
#define NH 32
#define NKV 8
#define HD 128
#define NREP 4
#define MTOK 4096  // BSZ*SEQ

// ---------------- device scratch (allocation-free) ----------------
__device__ float g_q[(size_t)MTOK * NH * HD];
__device__ float g_k[(size_t)MTOK * NKV * HD];
__device__ float g_v[(size_t)MTOK * NKV * HD];
__device__ float g_o[(size_t)MTOK * NH * HD];

__device__ uint16_t g_xh[(size_t)MTOK * DIM], g_xl[(size_t)MTOK * DIM];
__device__ uint16_t g_wqh[(size_t)DIM * DIM], g_wql[(size_t)DIM * DIM];              // [N][K]
__device__ uint16_t g_wkh[(size_t)DIM * NKV * HD], g_wkl[(size_t)DIM * NKV * HD];    // [N][K]
__device__ uint16_t g_wvh[(size_t)DIM * NKV * HD], g_wvl[(size_t)DIM * NKV * HD];    // [N][K]
__device__ uint16_t g_woh[(size_t)DIM * DIM], g_wol[(size_t)DIM * DIM];              // [N][K]
__device__ uint16_t g_ooh[(size_t)MTOK * DIM], g_ool[(size_t)MTOK * DIM];

// attention operands (post-RoPE, split)
__device__ uint16_t g_qsh[(size_t)MTOK * NH * HD], g_qsl[(size_t)MTOK * NH * HD];    // scaled by 1/sqrt(d)
__device__ uint16_t g_ksh[(size_t)MTOK * NKV * HD], g_ksl[(size_t)MTOK * NKV * HD];
__device__ uint16_t g_vth[(size_t)BSZ * NKV * HD * SEQ], g_vtl[(size_t)BSZ * NKV * HD * SEQ];  // [b][kvh][d][s]

// ---------------- helpers ----------------
__device__ __forceinline__ void fsplit(float v, uint16_t& hb, uint16_t& lb) {
    __nv_bfloat16 h = __float2bfloat16(v);
    float r = v - __bfloat162float(h);
    hb = __bfloat16_as_ushort(h);
    lb = __bfloat16_as_ushort(__float2bfloat16(r));
}

__device__ __forceinline__ void cpasync16(void* dst, const void* src) {
    uint32_t d = (uint32_t)__cvta_generic_to_shared(dst);
    asm volatile("cp.async.cg.shared.global [%0], [%1], 16;\n" ::"r"(d), "l"(src));
}
#define CPCOMMIT asm volatile("cp.async.commit_group;\n" ::)
#define CPWAIT0 asm volatile("cp.async.wait_group 0;\n" ::)

__device__ __forceinline__ void ldsm4(uint32_t* d, uint32_t addr) {
    asm volatile("ldmatrix.sync.aligned.m8n8.x4.shared.b16 {%0,%1,%2,%3}, [%4];"
                 : "=r"(d[0]), "=r"(d[1]), "=r"(d[2]), "=r"(d[3])
                 : "r"(addr));
}

__device__ __forceinline__ void mma_bs(float* c, const uint32_t* a, uint32_t b0, uint32_t b1) {
    asm volatile(
        "mma.sync.aligned.m16n8k16.row.col.f32.bf16.bf16.f32 "
        "{%0,%1,%2,%3}, {%4,%5,%6,%7}, {%8,%9}, {%0,%1,%2,%3};"
        : "+f"(c[0]), "+f"(c[1]), "+f"(c[2]), "+f"(c[3])
        : "r"(a[0]), "r"(a[1]), "r"(a[2]), "r"(a[3]), "r"(b0), "r"(b1));
}

// ---------------- prep kernels ----------------
__global__ void split_f32(const float* __restrict__ src, uint16_t* __restrict__ h,
                          uint16_t* __restrict__ l, size_t n4, float scale) {
    size_t i = (size_t)blockIdx.x * blockDim.x + threadIdx.x;
    if (i >= n4) return;
    float4 v = *(const float4*)(src + i * 4);
    ushort4 hh, ll;
    fsplit(v.x * scale, hh.x, ll.x);
    fsplit(v.y * scale, hh.y, ll.y);
    fsplit(v.z * scale, hh.z, ll.z);
    fsplit(v.w * scale, hh.w, ll.w);
    *(ushort4*)(h + i * 4) = hh;
    *(ushort4*)(l + i * 4) = ll;
}

// wh[n][k] = split(w[k][n]);  w is [K][N]
__global__ void tsplit_w(const float* __restrict__ w, uint16_t* __restrict__ wh,
                         uint16_t* __restrict__ wl, int K, int N) {
    __shared__ float t[32][33];
    int n0 = blockIdx.x * 32, k0 = blockIdx.y * 32;
    int tx = threadIdx.x, ty = threadIdx.y;
#pragma unroll
    for (int i = 0; i < 32; i += 8)
        t[ty + i][tx] = w[(size_t)(k0 + ty + i) * N + n0 + tx];
    __syncthreads();
#pragma unroll
    for (int i = 0; i < 32; i += 8) {
        int nn = ty + i, kk = tx;
        uint16_t hb, lb;
        fsplit(t[kk][nn], hb, lb);
        wh[(size_t)(n0 + nn) * K + k0 + kk] = hb;
        wl[(size_t)(n0 + nn) * K + k0 + kk] = lb;
    }
}

// vt[b][kvh][d][s] = split(v[b*s][kvh][d])  (transpose d<->s)
__global__ void vtsplit(const float* __restrict__ v, uint16_t* __restrict__ vth,
                        uint16_t* __restrict__ vtl) {
    __shared__ float t[32][33];
    int bkv = blockIdx.z;
    int b = bkv / NKV, kvh = bkv % NKV;
    int d0 = blockIdx.x * 32, s0 = blockIdx.y * 32;
    int tx = threadIdx.x, ty = threadIdx.y;
#pragma unroll
    for (int i = 0; i < 32; i += 8)
        t[ty + i][tx] = v[((size_t)(b * SEQ + s0 + ty + i) * NKV + kvh) * HD + d0 + tx];  // t[s][d]
    __syncthreads();
#pragma unroll
    for (int i = 0; i < 32; i += 8) {
        int d = ty + i, s = tx;
        uint16_t hb, lb;
        fsplit(t[s][d], hb, lb);
        size_t o = (((size_t)(b * NKV + kvh) * HD + d0 + d) * SEQ) + s0 + s;
        vth[o] = hb;
        vtl[o] = lb;
    }
}

// ---------------------------------------------------------------------------
// hi/lo-split bf16 tensor-core GEMM (validated round 4): C[M,N] = A[M,K] @ B[N,K]^T
// ---------------------------------------------------------------------------
__global__ void __launch_bounds__(256) hgemm(
    const uint16_t* __restrict__ Ah, const uint16_t* __restrict__ Al,
    const uint16_t* __restrict__ Bh, const uint16_t* __restrict__ Bl,
    float* __restrict__ C, int M, int N, int K) {
    extern __shared__ uint16_t smem[];
    const int tid = threadIdx.x, lane = tid & 31, warp = tid >> 5;
    const int wm = warp >> 1, wn = warp & 1;
    const size_t Arow0 = (size_t)blockIdx.y * 128;
    const size_t Brow0 = (size_t)blockIdx.x * 128;

    float acc[2][8][4];
#pragma unroll
    for (int mt = 0; mt < 2; mt++)
#pragma unroll
        for (int nt = 0; nt < 8; nt++)
#pragma unroll
            for (int i = 0; i < 4; i++) acc[mt][nt][i] = 0.0f;

    auto load_stage = [&](int st, int k0) {
        uint16_t* s = smem + st * 16384;
#pragma unroll
        for (int i = 0; i < 2; i++) {
            int idx = tid + i * 256;
            int r = idx >> 2, c = idx & 3;
            int sc = c ^ ((r >> 1) & 3);
            cpasync16(s + r * 32 + sc * 8, Ah + (Arow0 + r) * K + k0 + c * 8);
            cpasync16(s + 4096 + r * 32 + sc * 8, Al + (Arow0 + r) * K + k0 + c * 8);
            cpasync16(s + 8192 + r * 32 + sc * 8, Bh + (Brow0 + r) * K + k0 + c * 8);
            cpasync16(s + 12288 + r * 32 + sc * 8, Bl + (Brow0 + r) * K + k0 + c * 8);
        }
    };

    auto compute_stage = [&](int st) {
        uint16_t* s = smem + st * 16384;
#pragma unroll
        for (int ks = 0; ks < 2; ks++) {
            uint32_t af[2][2][4];
#pragma unroll
            for (int mt = 0; mt < 2; mt++) {
                int r = wm * 32 + mt * 16 + (lane & 15);
                int c = ks * 2 + (lane >> 4);
                int sc = c ^ ((r >> 1) & 3);
                uint32_t a0 = (uint32_t)__cvta_generic_to_shared(s + r * 32 + sc * 8);
                ldsm4(af[0][mt], a0);
                ldsm4(af[1][mt], a0 + 4096 * 2);
            }
            uint32_t bf[2][4][4];
#pragma unroll
            for (int np = 0; np < 4; np++) {
                int r = wn * 64 + np * 16 + ((lane >> 4) & 1) * 8 + (lane & 7);
                int c = ks * 2 + ((lane >> 3) & 1);
                int sc = c ^ ((r >> 1) & 3);
                uint32_t a0 = (uint32_t)__cvta_generic_to_shared(s + 8192 + r * 32 + sc * 8);
                ldsm4(bf[0][np], a0);
                ldsm4(bf[1][np], a0 + 4096 * 2);
            }
#pragma unroll
            for (int mt = 0; mt < 2; mt++)
#pragma unroll
                for (int nt = 0; nt < 8; nt++) {
                    uint32_t b0h = bf[0][nt >> 1][(nt & 1) * 2];
                    uint32_t b1h = bf[0][nt >> 1][(nt & 1) * 2 + 1];
                    uint32_t b0l = bf[1][nt >> 1][(nt & 1) * 2];
                    uint32_t b1l = bf[1][nt >> 1][(nt & 1) * 2 + 1];
                    mma_bs(acc[mt][nt], af[0][mt], b0h, b1h);
                    mma_bs(acc[mt][nt], af[1][mt], b0h, b1h);
                    mma_bs(acc[mt][nt], af[0][mt], b0l, b1l);
                }
        }
    };

    load_stage(0, 0);
    CPCOMMIT;
    const int NKI = K >> 5;
    for (int kt = 0; kt < NKI; kt++) {
        CPWAIT0;
        __syncthreads();
        if (kt + 1 < NKI) {
            load_stage((kt + 1) & 1, (kt + 1) * 32);
            CPCOMMIT;
        }
        compute_stage(kt & 1);
        __syncthreads();
    }

#pragma unroll
    for (int mt = 0; mt < 2; mt++)
#pragma unroll
        for (int nt = 0; nt < 8; nt++) {
            size_t row = Arow0 + wm * 32 + mt * 16 + (lane >> 2);
            size_t col = Brow0 + wn * 64 + nt * 8 + (lane & 3) * 2;
            *(float2*)&C[row * N + col] = make_float2(acc[mt][nt][0], acc[mt][nt][1]);
            *(float2*)&C[(row + 8) * N + col] = make_float2(acc[mt][nt][2], acc[mt][nt][3]);
        }
}

// ---------------------------------------------------------------------------
// RoPE (fp32)
// ---------------------------------------------------------------------------
__global__ void rope_kernel(float* __restrict__ t, const float* __restrict__ cosT,
                            const float* __restrict__ sinT, int nh, int total) {
    int i = blockIdx.x * blockDim.x + threadIdx.x;
    if (i >= total) return;
    int pair = i & 63;
    int h = (i >> 6) % nh;
    int bs = i / (64 * nh);
    int s = bs & (SEQ - 1);
    size_t base = ((size_t)bs * nh + h) * HD + 2 * pair;
    float a = t[base];
    float b = t[base + 1];
    float c = cosT[s * 64 + pair];
    float sn = sinT[s * 64 + pair];
    t[base] = a * c - b * sn;
    t[base + 1] = a * sn + b * c;
}

// ---------------------------------------------------------------------------
// Tensor-core flash attention. 64 q-rows per CTA, kv tiles of 64, 8 warps.
// Q/K/Vt/P all hi/lo split bf16; softmax fp32 per-row in smem.
// smem (halfs): Q[2 x 64*136], K[2 x 64*136], Vt[2 x 128*72], P[2 x 64*72],
// then fp32: Ss[64*68], m/l/f[64 each]. Total 143,104 B.
// ---------------------------------------------------------------------------
#define OQ1 8704
#define OK0 17408
#define OK1 26112
#define OV0 34816
#define OV1 44032
#define OP0 53248
#define OP1 57856
#define OF32 62464

__global__ void __launch_bounds__(256) attn_mma() {
    extern __shared__ uint16_t sm[];
    float* Ss = (float*)(sm + OF32);     // 64*68
    float* mRow = Ss + 64 * 68;
    float* lRow = mRow + 64;
    float* fRow = lRow + 64;

    const int tid = threadIdx.x, lane = tid & 31, warp = tid >> 5;
    const int wm = warp >> 1, wn = warp & 1;  // 4 x 2
    const int bh = blockIdx.x;
    const int b = bh / NH, h = bh % NH, kvh = h / NREP;
    const int qt = gridDim.y - 1 - blockIdx.y;
    const int q0 = qt * 64;

    // Q tile load (both planes), stays resident
    for (int i = tid; i < 1024; i += 256) {
        int r = i >> 4, c = i & 15;
        size_t src = ((size_t)(b * SEQ + q0 + r) * NH + h) * HD + c * 8;
        cpasync16(sm + r * 136 + c * 8, g_qsh + src);
        cpasync16(sm + OQ1 + r * 136 + c * 8, g_qsl + src);
    }
    CPCOMMIT;
    if (tid < 64) {
        mRow[tid] = -1e30f;
        lRow[tid] = 0.0f;
    }

    float oacc[8][4];
#pragma unroll
    for (int nt = 0; nt < 8; nt++)
#pragma unroll
        for (int i = 0; i < 4; i++) oacc[nt][i] = 0.0f;

    for (int kt = 0; kt <= qt; kt++) {
        const int k0 = kt * 64;
        // K tile
        for (int i = tid; i < 1024; i += 256) {
            int r = i >> 4, c = i & 15;
            size_t src = ((size_t)(b * SEQ + k0 + r) * NKV + kvh) * HD + c * 8;
            cpasync16(sm + OK0 + r * 136 + c * 8, g_ksh + src);
            cpasync16(sm + OK1 + r * 136 + c * 8, g_ksl + src);
        }
        // V^T tile (128 d-rows x 64 s)
        for (int i = tid; i < 1024; i += 256) {
            int r = i >> 3, c = i & 7;
            size_t src = (((size_t)(b * NKV + kvh) * HD + r) * SEQ) + k0 + c * 8;
            cpasync16(sm + OV0 + r * 72 + c * 8, g_vth + src);
            cpasync16(sm + OV1 + r * 72 + c * 8, g_vtl + src);
        }
        CPCOMMIT;
        CPWAIT0;
        __syncthreads();

        // ---- S = Q @ K^T : warp tile 16m x 32n ----
        float sacc[4][4];
#pragma unroll
        for (int nt = 0; nt < 4; nt++)
#pragma unroll
            for (int i = 0; i < 4; i++) sacc[nt][i] = 0.0f;

#pragma unroll
        for (int ks = 0; ks < 8; ks++) {
            uint32_t aq[2][4];
            {
                int r = wm * 16 + (lane & 15);
                int c = ks * 2 + (lane >> 4);
                uint32_t a0 = (uint32_t)__cvta_generic_to_shared(sm + r * 136 + c * 8);
                ldsm4(aq[0], a0);
                ldsm4(aq[1], a0 + OQ1 * 2);
            }
            uint32_t bk[2][2][4];
#pragma unroll
            for (int np = 0; np < 2; np++) {
                int r = wn * 32 + np * 16 + ((lane >> 4) & 1) * 8 + (lane & 7);
                int c = ks * 2 + ((lane >> 3) & 1);
                uint32_t a0 = (uint32_t)__cvta_generic_to_shared(sm + OK0 + r * 136 + c * 8);
                ldsm4(bk[0][np], a0);
                ldsm4(bk[1][np], a0 + (OK1 - OK0) * 2);
            }
#pragma unroll
            for (int nt = 0; nt < 4; nt++) {
                uint32_t b0h = bk[0][nt >> 1][(nt & 1) * 2];
                uint32_t b1h = bk[0][nt >> 1][(nt & 1) * 2 + 1];
                uint32_t b0l = bk[1][nt >> 1][(nt & 1) * 2];
                uint32_t b1l = bk[1][nt >> 1][(nt & 1) * 2 + 1];
                mma_bs(sacc[nt], aq[0], b0h, b1h);
                mma_bs(sacc[nt], aq[1], b0h, b1h);
                mma_bs(sacc[nt], aq[0], b0l, b1l);
            }
        }

        // write S frags to smem
#pragma unroll
        for (int nt = 0; nt < 4; nt++) {
            int row = wm * 16 + (lane >> 2);
            int col = wn * 32 + nt * 8 + (lane & 3) * 2;
            *(float2*)&Ss[row * 68 + col] = make_float2(sacc[nt][0], sacc[nt][1]);
            *(float2*)&Ss[(row + 8) * 68 + col] = make_float2(sacc[nt][2], sacc[nt][3]);
        }
        __syncthreads();

        // ---- online softmax (one thread per q-row) ----
        if (tid < 64) {
            const int r = tid;
            const int jlim = (kt == qt) ? (r + 1) : 64;
            float m_old = mRow[r];
            float mx = m_old;
            for (int j = 0; j < jlim; j++) mx = fmaxf(mx, Ss[r * 68 + j]);
            float f = __expf(m_old - mx);
            float sum = 0.0f;
            for (int j = 0; j < 64; j++) {
                float e = (j < jlim) ? __expf(Ss[r * 68 + j] - mx) : 0.0f;
                sum += e;
                uint16_t hb, lb;
                fsplit(e, hb, lb);
                sm[OP0 + r * 72 + j] = hb;
                sm[OP1 + r * 72 + j] = lb;
            }
            mRow[r] = mx;
            lRow[r] = lRow[r] * f + sum;
            fRow[r] = f;
        }
        __syncthreads();

        // ---- rescale O, then O += P @ V : warp tile 16m x 64n ----
        {
            float f0 = fRow[wm * 16 + (lane >> 2)];
            float f1 = fRow[wm * 16 + (lane >> 2) + 8];
#pragma unroll
            for (int nt = 0; nt < 8; nt++) {
                oacc[nt][0] *= f0;
                oacc[nt][1] *= f0;
                oacc[nt][2] *= f1;
                oacc[nt][3] *= f1;
            }
        }
#pragma unroll
        for (int ks = 0; ks < 4; ks++) {
            uint32_t ap[2][4];
            {
                int r = wm * 16 + (lane & 15);
                int c = ks * 2 + (lane >> 4);
                uint32_t a0 = (uint32_t)__cvta_generic_to_shared(sm + OP0 + r * 72 + c * 8);
                ldsm4(ap[0], a0);
                ldsm4(ap[1], a0 + (OP1 - OP0) * 2);
            }
            uint32_t bv[2][4][4];
#pragma unroll
            for (int np = 0; np < 4; np++) {
                int r = wn * 64 + np * 16 + ((lane >> 4) & 1) * 8 + (lane & 7);
                int c = ks * 2 + ((lane >> 3) & 1);
                uint32_t a0 = (uint32_t)__cvta_generic_to_shared(sm + OV0 + r * 72 + c * 8);
                ldsm4(bv[0][np], a0);
                ldsm4(bv[1][np], a0 + (OV1 - OV0) * 2);
            }
#pragma unroll
            for (int nt = 0; nt < 8; nt++) {
                uint32_t b0h = bv[0][nt >> 1][(nt & 1) * 2];
                uint32_t b1h = bv[0][nt >> 1][(nt & 1) * 2 + 1];
                uint32_t b0l = bv[1][nt >> 1][(nt & 1) * 2];
                uint32_t b1l = bv[1][nt >> 1][(nt & 1) * 2 + 1];
                mma_bs(oacc[nt], ap[0], b0h, b1h);
                mma_bs(oacc[nt], ap[1], b0h, b1h);
                mma_bs(oacc[nt], ap[0], b0l, b1l);
            }
        }
        __syncthreads();
    }

    // epilogue: divide by l, store fp32 to g_o [b*s][h][d]
    {
        int row = wm * 16 + (lane >> 2);
        float l0 = 1.0f / lRow[row];
        float l1 = 1.0f / lRow[row + 8];
#pragma unroll
        for (int nt = 0; nt < 8; nt++) {
            int col = wn * 64 + nt * 8 + (lane & 3) * 2;
            float* d0 = g_o + ((size_t)(b * SEQ + q0 + row) * NH + h) * HD + col;
            float* d1 = g_o + ((size_t)(b * SEQ + q0 + row + 8) * NH + h) * HD + col;
            *(float2*)d0 = make_float2(oacc[nt][0] * l0, oacc[nt][1] * l0);
            *(float2*)d1 = make_float2(oacc[nt][2] * l1, oacc[nt][3] * l1);
        }
    }
}

// ---------------------------------------------------------------------------
extern "C" void kernel_launch(void* const* d_in, const int* in_sizes, int n_in,
                              void* d_out, int out_size) {
    const float* x = (const float*)d_in[0];
    const float* wq = (const float*)d_in[1];
    const float* wk = (const float*)d_in[2];
    const float* wv = (const float*)d_in[3];
    const float* wo = (const float*)d_in[4];
    const float* fcos = (const float*)d_in[7];
    const float* fsin = (const float*)d_in[8];
    float* out = (float*)d_out;

    float *q, *k, *v, *o;
    cudaGetSymbolAddress((void**)&q, g_q);
    cudaGetSymbolAddress((void**)&k, g_k);
    cudaGetSymbolAddress((void**)&v, g_v);
    cudaGetSymbolAddress((void**)&o, g_o);
    uint16_t *xh, *xl, *wqh, *wql, *wkh, *wkl, *wvh, *wvl, *woh, *wol, *ooh, *ool;
    uint16_t *qsh, *qsl, *ksh, *ksl, *vth, *vtl;
    cudaGetSymbolAddress((void**)&xh, g_xh);
    cudaGetSymbolAddress((void**)&xl, g_xl);
    cudaGetSymbolAddress((void**)&wqh, g_wqh);
    cudaGetSymbolAddress((void**)&wql, g_wql);
    cudaGetSymbolAddress((void**)&wkh, g_wkh);
    cudaGetSymbolAddress((void**)&wkl, g_wkl);
    cudaGetSymbolAddress((void**)&wvh, g_wvh);
    cudaGetSymbolAddress((void**)&wvl, g_wvl);
    cudaGetSymbolAddress((void**)&woh, g_woh);
    cudaGetSymbolAddress((void**)&wol, g_wol);
    cudaGetSymbolAddress((void**)&ooh, g_ooh);
    cudaGetSymbolAddress((void**)&ool, g_ool);
    cudaGetSymbolAddress((void**)&qsh, g_qsh);
    cudaGetSymbolAddress((void**)&qsl, g_qsl);
    cudaGetSymbolAddress((void**)&ksh, g_ksh);
    cudaGetSymbolAddress((void**)&ksl, g_ksl);
    cudaGetSymbolAddress((void**)&vth, g_vth);
    cudaGetSymbolAddress((void**)&vtl, g_vtl);

    const int M = MTOK;
    static bool attr_set = false;
    if (!attr_set) {
        cudaFuncSetAttribute(hgemm, cudaFuncAttributeMaxDynamicSharedMemorySize, 65536);
        cudaFuncSetAttribute(attn_mma, cudaFuncAttributeMaxDynamicSharedMemorySize, 143104);
        attr_set = true;
    }

    // Split x + transpose/split weights
    split_f32<<<(M * DIM / 4 + 255) / 256, 256>>>(x, xh, xl, (size_t)M * DIM / 4, 1.0f);
    tsplit_w<<<dim3(DIM / 32, DIM / 32), dim3(32, 8)>>>(wq, wqh, wql, DIM, DIM);
    tsplit_w<<<dim3(NKV * HD / 32, DIM / 32), dim3(32, 8)>>>(wk, wkh, wkl, DIM, NKV * HD);
    tsplit_w<<<dim3(NKV * HD / 32, DIM / 32), dim3(32, 8)>>>(wv, wvh, wvl, DIM, NKV * HD);
    tsplit_w<<<dim3(DIM / 32, DIM / 32), dim3(32, 8)>>>(wo, woh, wol, DIM, DIM);

    // QKV projections
    hgemm<<<dim3(DIM / 128, M / 128), 256, 65536>>>(xh, xl, wqh, wql, q, M, DIM, DIM);
    hgemm<<<dim3(NKV * HD / 128, M / 128), 256, 65536>>>(xh, xl, wkh, wkl, k, M, NKV * HD, DIM);
    hgemm<<<dim3(NKV * HD / 128, M / 128), 256, 65536>>>(xh, xl, wvh, wvl, v, M, NKV * HD, DIM);

    // RoPE
    {
        int totq = MTOK * NH * 64;
        rope_kernel<<<(totq + 255) / 256, 256>>>(q, fcos, fsin, NH, totq);
        int totk = MTOK * NKV * 64;
        rope_kernel<<<(totk + 255) / 256, 256>>>(k, fcos, fsin, NKV, totk);
    }

    // Split attention operands (Q pre-scaled by 1/sqrt(d)), V transposed-split
    split_f32<<<(M * NH * HD / 4 + 255) / 256, 256>>>(q, qsh, qsl, (size_t)M * NH * HD / 4,
                                                      0.08838834764831845f);
    split_f32<<<(M * NKV * HD / 4 + 255) / 256, 256>>>(k, ksh, ksl, (size_t)M * NKV * HD / 4, 1.0f);
    vtsplit<<<dim3(HD / 32, SEQ / 32, BSZ * NKV), dim3(32, 8)>>>(v, vth, vtl);

    // Tensor-core flash attention
    attn_mma<<<dim3(BSZ * NH, SEQ / 64), 256, 143104>>>();

    // O projection
    split_f32<<<(M * DIM / 4 + 255) / 256, 256>>>(o, ooh, ool, (size_t)M * DIM / 4, 1.0f);
    hgemm<<<dim3(DIM / 128, M / 128), 256, 65536>>>(ooh, ool, woh, wol, out, M, DIM, DIM);
}

// round 13
// speedup vs baseline: 4.5422x; 1.0924x over previous
#include <cuda_runtime.h>
#include <cuda_bf16.h>
#include <stdint.h>
#include <math.h>

#define BSZ 2
#define SEQ 2048
#define DIM 4096
#define NH 32
#define NKV 8
#define HD 128
#define NREP 4
#define MTOK 4096  // BSZ*SEQ

// ---------------- device scratch (allocation-free) ----------------
__device__ float g_q[(size_t)MTOK * NH * HD];
__device__ float g_k[(size_t)MTOK * NKV * HD];
__device__ float g_v[(size_t)MTOK * NKV * HD];

__device__ uint16_t g_xh[(size_t)MTOK * DIM], g_xl[(size_t)MTOK * DIM];
__device__ uint16_t g_wqh[(size_t)DIM * DIM], g_wql[(size_t)DIM * DIM];              // [N][K]
__device__ uint16_t g_wkh[(size_t)DIM * NKV * HD], g_wkl[(size_t)DIM * NKV * HD];    // [N][K]
__device__ uint16_t g_wvh[(size_t)DIM * NKV * HD], g_wvl[(size_t)DIM * NKV * HD];    // [N][K]
__device__ uint16_t g_woh[(size_t)DIM * DIM], g_wol[(size_t)DIM * DIM];              // [N][K]
__device__ uint16_t g_ooh[(size_t)MTOK * DIM], g_ool[(size_t)MTOK * DIM];

// attention operands (post-RoPE, split)
__device__ uint16_t g_qsh[(size_t)MTOK * NH * HD], g_qsl[(size_t)MTOK * NH * HD];    // scaled by 1/sqrt(d)
__device__ uint16_t g_ksh[(size_t)MTOK * NKV * HD], g_ksl[(size_t)MTOK * NKV * HD];
__device__ uint16_t g_vth[(size_t)BSZ * NKV * HD * SEQ], g_vtl[(size_t)BSZ * NKV * HD * SEQ];  // [b][kvh][d][s]

// ---------------- helpers ----------------
__device__ __forceinline__ void fsplit(float v, uint16_t& hb, uint16_t& lb) {
    __nv_bfloat16 h = __float2bfloat16(v);
    float r = v - __bfloat162float(h);
    hb = __bfloat16_as_ushort(h);
    lb = __bfloat16_as_ushort(__float2bfloat16(r));
}

__device__ __forceinline__ void cpasync16(void* dst, const void* src) {
    uint32_t d = (uint32_t)__cvta_generic_to_shared(dst);
    asm volatile("cp.async.cg.shared.global [%0], [%1], 16;\n" ::"r"(d), "l"(src));
}
#define CPCOMMIT asm volatile("cp.async.commit_group;\n" ::)
#define CPWAIT0 asm volatile("cp.async.wait_group 0;\n" ::)
#define CPWAIT1 asm volatile("cp.async.wait_group 1;\n" ::)

__device__ __forceinline__ void ldsm4(uint32_t* d, uint32_t addr) {
    asm volatile("ldmatrix.sync.aligned.m8n8.x4.shared.b16 {%0,%1,%2,%3}, [%4];"
                 : "=r"(d[0]), "=r"(d[1]), "=r"(d[2]), "=r"(d[3])
                 : "r"(addr));
}

__device__ __forceinline__ void mma_bs(float* c, const uint32_t* a, uint32_t b0, uint32_t b1) {
    asm volatile(
        "mma.sync.aligned.m16n8k16.row.col.f32.bf16.bf16.f32 "
        "{%0,%1,%2,%3}, {%4,%5,%6,%7}, {%8,%9}, {%0,%1,%2,%3};"
        : "+f"(c[0]), "+f"(c[1]), "+f"(c[2]), "+f"(c[3])
        : "r"(a[0]), "r"(a[1]), "r"(a[2]), "r"(a[3]), "r"(b0), "r"(b1));
}

// ---------------- prep kernels ----------------
__global__ void split_f32(const float* __restrict__ src, uint16_t* __restrict__ h,
                          uint16_t* __restrict__ l, size_t n4, float scale) {
    size_t i = (size_t)blockIdx.x * blockDim.x + threadIdx.x;
    if (i >= n4) return;
    float4 v = *(const float4*)(src + i * 4);
    ushort4 hh, ll;
    fsplit(v.x * scale, hh.x, ll.x);
    fsplit(v.y * scale, hh.y, ll.y);
    fsplit(v.z * scale, hh.z, ll.z);
    fsplit(v.w * scale, hh.w, ll.w);
    *(ushort4*)(h + i * 4) = hh;
    *(ushort4*)(l + i * 4) = ll;
}

// fused RoPE + scale + hi/lo split
__global__ void rope_split(const float* __restrict__ t, const float* __restrict__ cosT,
                           const float* __restrict__ sinT, uint16_t* __restrict__ oh,
                           uint16_t* __restrict__ ol, int nh, int total, float scale) {
    int i = blockIdx.x * blockDim.x + threadIdx.x;
    if (i >= total) return;
    int pair = i & 63;
    int h = (i >> 6) % nh;
    int bs = i / (64 * nh);
    int s = bs & (SEQ - 1);
    size_t base = ((size_t)bs * nh + h) * HD + 2 * pair;
    float a = t[base];
    float b = t[base + 1];
    float c = cosT[s * 64 + pair];
    float sn = sinT[s * 64 + pair];
    float x0 = (a * c - b * sn) * scale;
    float x1 = (a * sn + b * c) * scale;
    uint16_t h0, l0, h1, l1;
    fsplit(x0, h0, l0);
    fsplit(x1, h1, l1);
    *(ushort2*)(oh + base) = make_ushort2(h0, h1);
    *(ushort2*)(ol + base) = make_ushort2(l0, l1);
}

// wh[n][k] = split(w[k][n]);  w is [K][N]
__global__ void tsplit_w(const float* __restrict__ w, uint16_t* __restrict__ wh,
                         uint16_t* __restrict__ wl, int K, int N) {
    __shared__ float t[32][33];
    int n0 = blockIdx.x * 32, k0 = blockIdx.y * 32;
    int tx = threadIdx.x, ty = threadIdx.y;
#pragma unroll
    for (int i = 0; i < 32; i += 8)
        t[ty + i][tx] = w[(size_t)(k0 + ty + i) * N + n0 + tx];
    __syncthreads();
#pragma unroll
    for (int i = 0; i < 32; i += 8) {
        int nn = ty + i, kk = tx;
        uint16_t hb, lb;
        fsplit(t[kk][nn], hb, lb);
        wh[(size_t)(n0 + nn) * K + k0 + kk] = hb;
        wl[(size_t)(n0 + nn) * K + k0 + kk] = lb;
    }
}

// vt[b][kvh][d][s] = split(v[b*s][kvh][d])  (transpose d<->s)
__global__ void vtsplit(const float* __restrict__ v, uint16_t* __restrict__ vth,
                        uint16_t* __restrict__ vtl) {
    __shared__ float t[32][33];
    int bkv = blockIdx.z;
    int b = bkv / NKV, kvh = bkv % NKV;
    int d0 = blockIdx.x * 32, s0 = blockIdx.y * 32;
    int tx = threadIdx.x, ty = threadIdx.y;
#pragma unroll
    for (int i = 0; i < 32; i += 8)
        t[ty + i][tx] = v[((size_t)(b * SEQ + s0 + ty + i) * NKV + kvh) * HD + d0 + tx];  // t[s][d]
    __syncthreads();
#pragma unroll
    for (int i = 0; i < 32; i += 8) {
        int d = ty + i, s = tx;
        uint16_t hb, lb;
        fsplit(t[s][d], hb, lb);
        size_t o = (((size_t)(b * NKV + kvh) * HD + d0 + d) * SEQ) + s0 + s;
        vth[o] = hb;
        vtl[o] = lb;
    }
}

// ---------------------------------------------------------------------------
// hi/lo-split bf16 tensor-core GEMM: C[M,N] = A[M,K] @ B[N,K]^T
// 128x128 CTA tile, BK=32, 8 warps, 3-stage cp.async pipeline.
// ---------------------------------------------------------------------------
__global__ void __launch_bounds__(256) hgemm(
    const uint16_t* __restrict__ Ah, const uint16_t* __restrict__ Al,
    const uint16_t* __restrict__ Bh, const uint16_t* __restrict__ Bl,
    float* __restrict__ C, int M, int N, int K) {
    extern __shared__ uint16_t smem[];  // 3 stages * 16384 u16
    const int tid = threadIdx.x, lane = tid & 31, warp = tid >> 5;
    const int wm = warp >> 1, wn = warp & 1;
    const size_t Arow0 = (size_t)blockIdx.y * 128;
    const size_t Brow0 = (size_t)blockIdx.x * 128;

    float acc[2][8][4];
#pragma unroll
    for (int mt = 0; mt < 2; mt++)
#pragma unroll
        for (int nt = 0; nt < 8; nt++)
#pragma unroll
            for (int i = 0; i < 4; i++) acc[mt][nt][i] = 0.0f;

    auto load_stage = [&](int st, int k0) {
        uint16_t* s = smem + st * 16384;
#pragma unroll
        for (int i = 0; i < 2; i++) {
            int idx = tid + i * 256;
            int r = idx >> 2, c = idx & 3;
            int sc = c ^ ((r >> 1) & 3);
            cpasync16(s + r * 32 + sc * 8, Ah + (Arow0 + r) * K + k0 + c * 8);
            cpasync16(s + 4096 + r * 32 + sc * 8, Al + (Arow0 + r) * K + k0 + c * 8);
            cpasync16(s + 8192 + r * 32 + sc * 8, Bh + (Brow0 + r) * K + k0 + c * 8);
            cpasync16(s + 12288 + r * 32 + sc * 8, Bl + (Brow0 + r) * K + k0 + c * 8);
        }
    };

    auto compute_stage = [&](int st) {
        uint16_t* s = smem + st * 16384;
#pragma unroll
        for (int ks = 0; ks < 2; ks++) {
            uint32_t af[2][2][4];
#pragma unroll
            for (int mt = 0; mt < 2; mt++) {
                int r = wm * 32 + mt * 16 + (lane & 15);
                int c = ks * 2 + (lane >> 4);
                int sc = c ^ ((r >> 1) & 3);
                uint32_t a0 = (uint32_t)__cvta_generic_to_shared(s + r * 32 + sc * 8);
                ldsm4(af[0][mt], a0);
                ldsm4(af[1][mt], a0 + 4096 * 2);
            }
            uint32_t bf[2][4][4];
#pragma unroll
            for (int np = 0; np < 4; np++) {
                int r = wn * 64 + np * 16 + ((lane >> 4) & 1) * 8 + (lane & 7);
                int c = ks * 2 + ((lane >> 3) & 1);
                int sc = c ^ ((r >> 1) & 3);
                uint32_t a0 = (uint32_t)__cvta_generic_to_shared(s + 8192 + r * 32 + sc * 8);
                ldsm4(bf[0][np], a0);
                ldsm4(bf[1][np], a0 + 4096 * 2);
            }
#pragma unroll
            for (int mt = 0; mt < 2; mt++)
#pragma unroll
                for (int nt = 0; nt < 8; nt++) {
                    uint32_t b0h = bf[0][nt >> 1][(nt & 1) * 2];
                    uint32_t b1h = bf[0][nt >> 1][(nt & 1) * 2 + 1];
                    uint32_t b0l = bf[1][nt >> 1][(nt & 1) * 2];
                    uint32_t b1l = bf[1][nt >> 1][(nt & 1) * 2 + 1];
                    mma_bs(acc[mt][nt], af[0][mt], b0h, b1h);
                    mma_bs(acc[mt][nt], af[1][mt], b0h, b1h);
                    mma_bs(acc[mt][nt], af[0][mt], b0l, b1l);
                }
        }
    };

    const int NKI = K >> 5;
    load_stage(0, 0);
    CPCOMMIT;
    if (NKI > 1) {
        load_stage(1, 32);
        CPCOMMIT;
    }
    for (int kt = 0; kt < NKI; kt++) {
        if (kt + 1 < NKI) {
            CPWAIT1;
        } else {
            CPWAIT0;
        }
        __syncthreads();
        if (kt + 2 < NKI) {
            load_stage((kt + 2) % 3, (kt + 2) * 32);
            CPCOMMIT;
        }
        compute_stage(kt % 3);
        __syncthreads();
    }

#pragma unroll
    for (int mt = 0; mt < 2; mt++)
#pragma unroll
        for (int nt = 0; nt < 8; nt++) {
            size_t row = Arow0 + wm * 32 + mt * 16 + (lane >> 2);
            size_t col = Brow0 + wn * 64 + nt * 8 + (lane & 3) * 2;
            *(float2*)&C[row * N + col] = make_float2(acc[mt][nt][0], acc[mt][nt][1]);
            *(float2*)&C[(row + 8) * N + col] = make_float2(acc[mt][nt][2], acc[mt][nt][3]);
        }
}

// ---------------------------------------------------------------------------
// Tensor-core flash attention. 64 q-rows/CTA, kv tiles of 64, 8 warps.
// KV double-buffered via cp.async groups; parallel online softmax (4 thr/row);
// epilogue writes hi/lo-split bf16 directly to g_ooh/g_ool.
// smem halfs: Q[2pl x 64*136] @0/8704; K[2st x 2pl x 64*136] @17408 (+st*17408);
// V[2st x 2pl x 128*72] @52224 (+st*18432); P[2pl x 64*72] @89088/93696;
// fp32 @98304: Ss[64*68], m/l/f[64]. Total 214,784 B.
// ---------------------------------------------------------------------------
#define AQ_OQ1 8704
#define AQ_OK 17408
#define AQ_OV 52224
#define AQ_OP0 89088
#define AQ_OP1 93696
#define AQ_OF32 98304
#define ATTN_SMEM 214784

__global__ void __launch_bounds__(256) attn_mma() {
    extern __shared__ uint16_t sm[];
    float* Ss = (float*)(sm + AQ_OF32);  // 64*68
    float* mRow = Ss + 64 * 68;
    float* lRow = mRow + 64;
    float* fRow = lRow + 64;

    const int tid = threadIdx.x, lane = tid & 31, warp = tid >> 5;
    const int wm = warp >> 1, wn = warp & 1;  // 4 x 2
    const int bh = blockIdx.x;
    const int b = bh / NH, h = bh % NH, kvh = h / NREP;
    const int qt = gridDim.y - 1 - blockIdx.y;
    const int q0 = qt * 64;

    // Q tile load (group 0), stays resident
    for (int i = tid; i < 1024; i += 256) {
        int r = i >> 4, c = i & 15;
        size_t src = ((size_t)(b * SEQ + q0 + r) * NH + h) * HD + c * 8;
        cpasync16(sm + r * 136 + c * 8, g_qsh + src);
        cpasync16(sm + AQ_OQ1 + r * 136 + c * 8, g_qsl + src);
    }
    CPCOMMIT;

    auto load_kv = [&](int kt, int st) {
        const int k0 = kt * 64;
        uint16_t* kb = sm + AQ_OK + st * 17408;
        uint16_t* vb = sm + AQ_OV + st * 18432;
        for (int i = tid; i < 1024; i += 256) {
            int r = i >> 4, c = i & 15;
            size_t src = ((size_t)(b * SEQ + k0 + r) * NKV + kvh) * HD + c * 8;
            cpasync16(kb + r * 136 + c * 8, g_ksh + src);
            cpasync16(kb + 8704 + r * 136 + c * 8, g_ksl + src);
        }
        for (int i = tid; i < 1024; i += 256) {
            int r = i >> 3, c = i & 7;
            size_t src = (((size_t)(b * NKV + kvh) * HD + r) * SEQ) + k0 + c * 8;
            cpasync16(vb + r * 72 + c * 8, g_vth + src);
            cpasync16(vb + 9216 + r * 72 + c * 8, g_vtl + src);
        }
    };

    load_kv(0, 0);
    CPCOMMIT;

    if (tid < 64) {
        mRow[tid] = -1e30f;
        lRow[tid] = 0.0f;
    }

    float oacc[8][4];
#pragma unroll
    for (int nt = 0; nt < 8; nt++)
#pragma unroll
        for (int i = 0; i < 4; i++) oacc[nt][i] = 0.0f;

    for (int kt = 0; kt <= qt; kt++) {
        const int st = kt & 1;
        if (kt < qt) {
            load_kv(kt + 1, st ^ 1);
            CPCOMMIT;
            CPWAIT1;
        } else {
            CPWAIT0;
        }
        __syncthreads();

        uint16_t* kb = sm + AQ_OK + st * 17408;
        uint16_t* vb = sm + AQ_OV + st * 18432;

        // ---- S = Q @ K^T : warp tile 16m x 32n ----
        float sacc[4][4];
#pragma unroll
        for (int nt = 0; nt < 4; nt++)
#pragma unroll
            for (int i = 0; i < 4; i++) sacc[nt][i] = 0.0f;

#pragma unroll
        for (int ks = 0; ks < 8; ks++) {
            uint32_t aq[2][4];
            {
                int r = wm * 16 + (lane & 15);
                int c = ks * 2 + (lane >> 4);
                uint32_t a0 = (uint32_t)__cvta_generic_to_shared(sm + r * 136 + c * 8);
                ldsm4(aq[0], a0);
                ldsm4(aq[1], a0 + AQ_OQ1 * 2);
            }
            uint32_t bk[2][2][4];
#pragma unroll
            for (int np = 0; np < 2; np++) {
                int r = wn * 32 + np * 16 + ((lane >> 4) & 1) * 8 + (lane & 7);
                int c = ks * 2 + ((lane >> 3) & 1);
                uint32_t a0 = (uint32_t)__cvta_generic_to_shared(kb + r * 136 + c * 8);
                ldsm4(bk[0][np], a0);
                ldsm4(bk[1][np], a0 + 8704 * 2);
            }
#pragma unroll
            for (int nt = 0; nt < 4; nt++) {
                uint32_t b0h = bk[0][nt >> 1][(nt & 1) * 2];
                uint32_t b1h = bk[0][nt >> 1][(nt & 1) * 2 + 1];
                uint32_t b0l = bk[1][nt >> 1][(nt & 1) * 2];
                uint32_t b1l = bk[1][nt >> 1][(nt & 1) * 2 + 1];
                mma_bs(sacc[nt], aq[0], b0h, b1h);
                mma_bs(sacc[nt], aq[1], b0h, b1h);
                mma_bs(sacc[nt], aq[0], b0l, b1l);
            }
        }

        // write S frags to smem
#pragma unroll
        for (int nt = 0; nt < 4; nt++) {
            int row = wm * 16 + (lane >> 2);
            int col = wn * 32 + nt * 8 + (lane & 3) * 2;
            *(float2*)&Ss[row * 68 + col] = make_float2(sacc[nt][0], sacc[nt][1]);
            *(float2*)&Ss[(row + 8) * 68 + col] = make_float2(sacc[nt][2], sacc[nt][3]);
        }
        __syncthreads();

        // ---- parallel online softmax: 4 threads per q-row ----
        {
            const int r = tid >> 2, qq = tid & 3;
            const int jlim = (kt == qt) ? (r + 1) : 64;
            float mx = -1e30f;
#pragma unroll
            for (int j4 = 0; j4 < 16; j4++) {
                int j = qq * 16 + j4;
                if (j < jlim) mx = fmaxf(mx, Ss[r * 68 + j]);
            }
            mx = fmaxf(mx, __shfl_xor_sync(0xffffffffu, mx, 1));
            mx = fmaxf(mx, __shfl_xor_sync(0xffffffffu, mx, 2));
            float m_old = mRow[r];
            float mnew = fmaxf(m_old, mx);
            float sum = 0.0f;
#pragma unroll
            for (int j4 = 0; j4 < 16; j4++) {
                int j = qq * 16 + j4;
                float e = (j < jlim) ? __expf(Ss[r * 68 + j] - mnew) : 0.0f;
                sum += e;
                uint16_t hb, lb;
                fsplit(e, hb, lb);
                sm[AQ_OP0 + r * 72 + j] = hb;
                sm[AQ_OP1 + r * 72 + j] = lb;
            }
            sum += __shfl_xor_sync(0xffffffffu, sum, 1);
            sum += __shfl_xor_sync(0xffffffffu, sum, 2);
            if (qq == 0) {
                float f = __expf(m_old - mnew);
                mRow[r] = mnew;
                lRow[r] = lRow[r] * f + sum;
                fRow[r] = f;
            }
        }
        __syncthreads();

        // ---- rescale O, then O += P @ V : warp tile 16m x 64n ----
        {
            float f0 = fRow[wm * 16 + (lane >> 2)];
            float f1 = fRow[wm * 16 + (lane >> 2) + 8];
#pragma unroll
            for (int nt = 0; nt < 8; nt++) {
                oacc[nt][0] *= f0;
                oacc[nt][1] *= f0;
                oacc[nt][2] *= f1;
                oacc[nt][3] *= f1;
            }
        }
#pragma unroll
        for (int ks = 0; ks < 4; ks++) {
            uint32_t ap[2][4];
            {
                int r = wm * 16 + (lane & 15);
                int c = ks * 2 + (lane >> 4);
                uint32_t a0 = (uint32_t)__cvta_generic_to_shared(sm + AQ_OP0 + r * 72 + c * 8);
                ldsm4(ap[0], a0);
                ldsm4(ap[1], a0 + (AQ_OP1 - AQ_OP0) * 2);
            }
            uint32_t bv[2][4][4];
#pragma unroll
            for (int np = 0; np < 4; np++) {
                int r = wn * 64 + np * 16 + ((lane >> 4) & 1) * 8 + (lane & 7);
                int c = ks * 2 + ((lane >> 3) & 1);
                uint32_t a0 = (uint32_t)__cvta_generic_to_shared(vb + r * 72 + c * 8);
                ldsm4(bv[0][np], a0);
                ldsm4(bv[1][np], a0 + 9216 * 2);
            }
#pragma unroll
            for (int nt = 0; nt < 8; nt++) {
                uint32_t b0h = bv[0][nt >> 1][(nt & 1) * 2];
                uint32_t b1h = bv[0][nt >> 1][(nt & 1) * 2 + 1];
                uint32_t b0l = bv[1][nt >> 1][(nt & 1) * 2];
                uint32_t b1l = bv[1][nt >> 1][(nt & 1) * 2 + 1];
                mma_bs(oacc[nt], ap[0], b0h, b1h);
                mma_bs(oacc[nt], ap[1], b0h, b1h);
                mma_bs(oacc[nt], ap[0], b0l, b1l);
            }
        }
        __syncthreads();
    }

    // epilogue: divide by l, split to bf16 hi/lo, store to g_ooh/g_ool [b*s][h*HD]
    {
        int row = wm * 16 + (lane >> 2);
        float li0 = 1.0f / lRow[row];
        float li1 = 1.0f / lRow[row + 8];
#pragma unroll
        for (int nt = 0; nt < 8; nt++) {
            int col = wn * 64 + nt * 8 + (lane & 3) * 2;
            size_t b0 = ((size_t)(b * SEQ + q0 + row) * NH + h) * HD + col;
            size_t b1 = ((size_t)(b * SEQ + q0 + row + 8) * NH + h) * HD + col;
            uint16_t ha, la, hbb, lbb;
            fsplit(oacc[nt][0] * li0, ha, la);
            fsplit(oacc[nt][1] * li0, hbb, lbb);
            *(ushort2*)(g_ooh + b0) = make_ushort2(ha, hbb);
            *(ushort2*)(g_ool + b0) = make_ushort2(la, lbb);
            fsplit(oacc[nt][2] * li1, ha, la);
            fsplit(oacc[nt][3] * li1, hbb, lbb);
            *(ushort2*)(g_ooh + b1) = make_ushort2(ha, hbb);
            *(ushort2*)(g_ool + b1) = make_ushort2(la, lbb);
        }
    }
}

// ---------------------------------------------------------------------------
extern "C" void kernel_launch(void* const* d_in, const int* in_sizes, int n_in,
                              void* d_out, int out_size) {
    const float* x = (const float*)d_in[0];
    const float* wq = (const float*)d_in[1];
    const float* wk = (const float*)d_in[2];
    const float* wv = (const float*)d_in[3];
    const float* wo = (const float*)d_in[4];
    const float* fcos = (const float*)d_in[7];
    const float* fsin = (const float*)d_in[8];
    float* out = (float*)d_out;

    float *q, *k, *v;
    cudaGetSymbolAddress((void**)&q, g_q);
    cudaGetSymbolAddress((void**)&k, g_k);
    cudaGetSymbolAddress((void**)&v, g_v);
    uint16_t *xh, *xl, *wqh, *wql, *wkh, *wkl, *wvh, *wvl, *woh, *wol, *ooh, *ool;
    uint16_t *qsh, *qsl, *ksh, *ksl, *vth, *vtl;
    cudaGetSymbolAddress((void**)&xh, g_xh);
    cudaGetSymbolAddress((void**)&xl, g_xl);
    cudaGetSymbolAddress((void**)&wqh, g_wqh);
    cudaGetSymbolAddress((void**)&wql, g_wql);
    cudaGetSymbolAddress((void**)&wkh, g_wkh);
    cudaGetSymbolAddress((void**)&wkl, g_wkl);
    cudaGetSymbolAddress((void**)&wvh, g_wvh);
    cudaGetSymbolAddress((void**)&wvl, g_wvl);
    cudaGetSymbolAddress((void**)&woh, g_woh);
    cudaGetSymbolAddress((void**)&wol, g_wol);
    cudaGetSymbolAddress((void**)&ooh, g_ooh);
    cudaGetSymbolAddress((void**)&ool, g_ool);
    cudaGetSymbolAddress((void**)&qsh, g_qsh);
    cudaGetSymbolAddress((void**)&qsl, g_qsl);
    cudaGetSymbolAddress((void**)&ksh, g_ksh);
    cudaGetSymbolAddress((void**)&ksl, g_ksl);
    cudaGetSymbolAddress((void**)&vth, g_vth);
    cudaGetSymbolAddress((void**)&vtl, g_vtl);

    const int M = MTOK;
    static bool attr_set = false;
    if (!attr_set) {
        cudaFuncSetAttribute(hgemm, cudaFuncAttributeMaxDynamicSharedMemorySize, 98304);
        cudaFuncSetAttribute(attn_mma, cudaFuncAttributeMaxDynamicSharedMemorySize, ATTN_SMEM);
        attr_set = true;
    }

    // Split x + transpose/split weights
    split_f32<<<(M * DIM / 4 + 255) / 256, 256>>>(x, xh, xl, (size_t)M * DIM / 4, 1.0f);
    tsplit_w<<<dim3(DIM / 32, DIM / 32), dim3(32, 8)>>>(wq, wqh, wql, DIM, DIM);
    tsplit_w<<<dim3(NKV * HD / 32, DIM / 32), dim3(32, 8)>>>(wk, wkh, wkl, DIM, NKV * HD);
    tsplit_w<<<dim3(NKV * HD / 32, DIM / 32), dim3(32, 8)>>>(wv, wvh, wvl, DIM, NKV * HD);
    tsplit_w<<<dim3(DIM / 32, DIM / 32), dim3(32, 8)>>>(wo, woh, wol, DIM, DIM);

    // QKV projections
    hgemm<<<dim3(DIM / 128, M / 128), 256, 98304>>>(xh, xl, wqh, wql, q, M, DIM, DIM);
    hgemm<<<dim3(NKV * HD / 128, M / 128), 256, 98304>>>(xh, xl, wkh, wkl, k, M, NKV * HD, DIM);
    hgemm<<<dim3(NKV * HD / 128, M / 128), 256, 98304>>>(xh, xl, wvh, wvl, v, M, NKV * HD, DIM);

    // Fused RoPE + scale + split (Q pre-scaled by 1/sqrt(d)); V transpose-split
    {
        int totq = MTOK * NH * 64;
        rope_split<<<(totq + 255) / 256, 256>>>(q, fcos, fsin, qsh, qsl, NH, totq,
                                                0.08838834764831845f);
        int totk = MTOK * NKV * 64;
        rope_split<<<(totk + 255) / 256, 256>>>(k, fcos, fsin, ksh, ksl, NKV, totk, 1.0f);
    }
    vtsplit<<<dim3(HD / 32, SEQ / 32, BSZ * NKV), dim3(32, 8)>>>(v, vth, vtl);

    // Tensor-core flash attention (writes split O directly)
    attn_mma<<<dim3(BSZ * NH, SEQ / 64), 256, ATTN_SMEM>>>();

    // O projection
    hgemm<<<dim3(DIM / 128, M / 128), 256, 98304>>>(ooh, ool, woh, wol, out, M, DIM, DIM);
}